// round 1
// baseline (speedup 1.0000x reference)
#include <cuda_runtime.h>
#include <cstdint>

#define NB   2048
#define NTOK 64
#define CDIM 512
#define NH   8
#define HD   64

#define SQ 68   // smem row stride (floats) for q1/q2/k1/attn tiles (bank-conflict-free frags)
#define SV 72   // smem row stride (floats) for v tile

// Precomputed bias[h][n][m] = bias_table[rel_index[n,m], h]  (128 KB, L2-resident)
__device__ float g_bias[NH * NTOK * NTOK];

__global__ void bias_precompute(const float* __restrict__ bias_table,
                                const int* __restrict__ rel_index) {
    int i = blockIdx.x * blockDim.x + threadIdx.x;
    if (i < NTOK * NTOK) {
        int ri = rel_index[i];
#pragma unroll
        for (int h = 0; h < NH; h++)
            g_bias[h * (NTOK * NTOK) + i] = bias_table[ri * NH + h];
    }
}

__device__ __forceinline__ float tf32r(float x) {
    uint32_t u;
    asm("cvt.rna.tf32.f32 %0, %1;" : "=r"(u) : "f"(x));
    return __uint_as_float(u);
}

__device__ __forceinline__ void mma_tf32(float c[4],
                                         uint32_t a0, uint32_t a1, uint32_t a2, uint32_t a3,
                                         uint32_t b0, uint32_t b1) {
    asm volatile(
        "mma.sync.aligned.m16n8k8.row.col.f32.tf32.tf32.f32 "
        "{%0,%1,%2,%3}, {%4,%5,%6,%7}, {%8,%9}, {%0,%1,%2,%3};\n"
        : "+f"(c[0]), "+f"(c[1]), "+f"(c[2]), "+f"(c[3])
        : "r"(a0), "r"(a1), "r"(a2), "r"(a3), "r"(b0), "r"(b1));
}

extern __shared__ float smem[];

__global__ __launch_bounds__(128)
void win_attn_kernel(const float* __restrict__ q1g,
                     const float* __restrict__ q2g,
                     const float* __restrict__ k1g,
                     const float* __restrict__ v1g,
                     const float* __restrict__ gating,
                     float* __restrict__ outg) {
    const int bh = blockIdx.x;
    const int b  = bh >> 3;
    const int h  = bh & 7;
    const int tid  = threadIdx.x;
    const int lane = tid & 31;
    const int warp = tid >> 5;
    const int qg = lane >> 2;   // group id (0..7)
    const int qc = lane & 3;    // thread-in-group (0..3)

    float* q1s = smem;
    float* q2s = q1s + NTOK * SQ;
    float* k1s = q2s + NTOK * SQ;
    float* ats = k1s + NTOK * SQ;
    float* vs  = ats + NTOK * SQ;

    // ---- stage global -> smem (tf32-rounded, SCALE folded into q) ----
    const size_t base = (size_t)b * NTOK * CDIM + (size_t)h * HD;
#pragma unroll 8
    for (int i = tid; i < NTOK * (HD / 4); i += 128) {
        const int r  = i >> 4;
        const int c4 = (i & 15) * 4;
        const size_t go = base + (size_t)r * CDIM + c4;
        float4 a = *(const float4*)(q1g + go);
        float4 bq = *(const float4*)(q2g + go);
        float4 kk = *(const float4*)(k1g + go);
        float4 vv = *(const float4*)(v1g + go);
        a.x = tf32r(a.x * 0.125f);  a.y = tf32r(a.y * 0.125f);
        a.z = tf32r(a.z * 0.125f);  a.w = tf32r(a.w * 0.125f);
        bq.x = tf32r(bq.x * 0.125f); bq.y = tf32r(bq.y * 0.125f);
        bq.z = tf32r(bq.z * 0.125f); bq.w = tf32r(bq.w * 0.125f);
        kk.x = tf32r(kk.x); kk.y = tf32r(kk.y); kk.z = tf32r(kk.z); kk.w = tf32r(kk.w);
        vv.x = tf32r(vv.x); vv.y = tf32r(vv.y); vv.z = tf32r(vv.z); vv.w = tf32r(vv.w);
        *(float4*)&q1s[r * SQ + c4] = a;
        *(float4*)&q2s[r * SQ + c4] = bq;
        *(float4*)&k1s[r * SQ + c4] = kk;
        *(float4*)&vs [r * SV + c4] = vv;
    }
    __syncthreads();

    const int ws = warp * 16;          // this warp's 16-row slab
    const int row_lo = ws + qg;
    const int row_hi = row_lo + 8;

    // ---- QK^T for both maps (m16n8k8 tf32, shared k1 B-frags) ----
    float C1[8][4], C2[8][4];
#pragma unroll
    for (int n = 0; n < 8; n++)
#pragma unroll
        for (int j = 0; j < 4; j++) { C1[n][j] = 0.f; C2[n][j] = 0.f; }

#pragma unroll
    for (int kk = 0; kk < 8; kk++) {
        const int k0 = kk * 8;
        const int ca = k0 + qc;
        uint32_t a1f[4], a2f[4];
        a1f[0] = __float_as_uint(q1s[row_lo * SQ + ca]);
        a1f[1] = __float_as_uint(q1s[row_hi * SQ + ca]);
        a1f[2] = __float_as_uint(q1s[row_lo * SQ + ca + 4]);
        a1f[3] = __float_as_uint(q1s[row_hi * SQ + ca + 4]);
        a2f[0] = __float_as_uint(q2s[row_lo * SQ + ca]);
        a2f[1] = __float_as_uint(q2s[row_hi * SQ + ca]);
        a2f[2] = __float_as_uint(q2s[row_lo * SQ + ca + 4]);
        a2f[3] = __float_as_uint(q2s[row_hi * SQ + ca + 4]);
#pragma unroll
        for (int n = 0; n < 8; n++) {
            const int tok = n * 8 + qg;
            uint32_t b0 = __float_as_uint(k1s[tok * SQ + k0 + qc]);
            uint32_t b1 = __float_as_uint(k1s[tok * SQ + k0 + qc + 4]);
            mma_tf32(C1[n], a1f[0], a1f[1], a1f[2], a1f[3], b0, b1);
            mma_tf32(C2[n], a2f[0], a2f[1], a2f[2], a2f[3], b0, b1);
        }
    }

    // ---- add bias (L2-resident) ----
    const float* bp_lo = g_bias + h * (NTOK * NTOK) + row_lo * NTOK + 2 * qc;
    const float* bp_hi = g_bias + h * (NTOK * NTOK) + row_hi * NTOK + 2 * qc;
#pragma unroll
    for (int n = 0; n < 8; n++) {
        float2 blo = *(const float2*)(bp_lo + n * 8);
        float2 bhi = *(const float2*)(bp_hi + n * 8);
        C1[n][0] += blo.x; C1[n][1] += blo.y; C1[n][2] += bhi.x; C1[n][3] += bhi.y;
        C2[n][0] += blo.x; C2[n][1] += blo.y; C2[n][2] += bhi.x; C2[n][3] += bhi.y;
    }

    // ---- dual softmax over fragments (row spread across a quad) ----
    float m1l = -1e30f, m1h = -1e30f, m2l = -1e30f, m2h = -1e30f;
#pragma unroll
    for (int n = 0; n < 8; n++) {
        m1l = fmaxf(m1l, fmaxf(C1[n][0], C1[n][1]));
        m1h = fmaxf(m1h, fmaxf(C1[n][2], C1[n][3]));
        m2l = fmaxf(m2l, fmaxf(C2[n][0], C2[n][1]));
        m2h = fmaxf(m2h, fmaxf(C2[n][2], C2[n][3]));
    }
#pragma unroll
    for (int off = 1; off <= 2; off <<= 1) {
        m1l = fmaxf(m1l, __shfl_xor_sync(0xffffffffu, m1l, off));
        m1h = fmaxf(m1h, __shfl_xor_sync(0xffffffffu, m1h, off));
        m2l = fmaxf(m2l, __shfl_xor_sync(0xffffffffu, m2l, off));
        m2h = fmaxf(m2h, __shfl_xor_sync(0xffffffffu, m2h, off));
    }

    float s1l = 0.f, s1h = 0.f, s2l = 0.f, s2h = 0.f;
#pragma unroll
    for (int n = 0; n < 8; n++) {
        C1[n][0] = __expf(C1[n][0] - m1l); s1l += C1[n][0];
        C1[n][1] = __expf(C1[n][1] - m1l); s1l += C1[n][1];
        C1[n][2] = __expf(C1[n][2] - m1h); s1h += C1[n][2];
        C1[n][3] = __expf(C1[n][3] - m1h); s1h += C1[n][3];
        C2[n][0] = __expf(C2[n][0] - m2l); s2l += C2[n][0];
        C2[n][1] = __expf(C2[n][1] - m2l); s2l += C2[n][1];
        C2[n][2] = __expf(C2[n][2] - m2h); s2h += C2[n][2];
        C2[n][3] = __expf(C2[n][3] - m2h); s2h += C2[n][3];
    }
#pragma unroll
    for (int off = 1; off <= 2; off <<= 1) {
        s1l += __shfl_xor_sync(0xffffffffu, s1l, off);
        s1h += __shfl_xor_sync(0xffffffffu, s1h, off);
        s2l += __shfl_xor_sync(0xffffffffu, s2l, off);
        s2h += __shfl_xor_sync(0xffffffffu, s2h, off);
    }

    // gate = sigmoid(gating[h]); mixed softmaxes each sum to 1 so the final
    // renormalization divides by exactly (1-g)+g = 1 -> skip it.
    const float gp = gating[h];
    const float gv = 1.0f / (1.0f + __expf(-gp));
    const float w1l = (1.0f - gv) / s1l, w1h = (1.0f - gv) / s1h;
    const float w2l = gv / s2l,          w2h = gv / s2h;

    // mixed attention -> warp-private smem slab (tf32-rounded)
#pragma unroll
    for (int n = 0; n < 8; n++) {
        float2 lo, hi;
        lo.x = tf32r(C1[n][0] * w1l + C2[n][0] * w2l);
        lo.y = tf32r(C1[n][1] * w1l + C2[n][1] * w2l);
        hi.x = tf32r(C1[n][2] * w1h + C2[n][2] * w2h);
        hi.y = tf32r(C1[n][3] * w1h + C2[n][3] * w2h);
        *(float2*)&ats[row_lo * SQ + n * 8 + 2 * qc] = lo;
        *(float2*)&ats[row_hi * SQ + n * 8 + 2 * qc] = hi;
    }
    __syncwarp();

    // ---- O = attn @ V ----
    float O[8][4];
#pragma unroll
    for (int n = 0; n < 8; n++)
#pragma unroll
        for (int j = 0; j < 4; j++) O[n][j] = 0.f;

#pragma unroll
    for (int kk = 0; kk < 8; kk++) {
        const int k0 = kk * 8;
        const int ca = k0 + qc;
        uint32_t af[4];
        af[0] = __float_as_uint(ats[row_lo * SQ + ca]);
        af[1] = __float_as_uint(ats[row_hi * SQ + ca]);
        af[2] = __float_as_uint(ats[row_lo * SQ + ca + 4]);
        af[3] = __float_as_uint(ats[row_hi * SQ + ca + 4]);
#pragma unroll
        for (int n = 0; n < 8; n++) {
            const int dcol = n * 8 + qg;
            uint32_t b0 = __float_as_uint(vs[(k0 + qc) * SV + dcol]);
            uint32_t b1 = __float_as_uint(vs[(k0 + qc + 4) * SV + dcol]);
            mma_tf32(O[n], af[0], af[1], af[2], af[3], b0, b1);
        }
    }

    // ---- store output: out[b, row, h*64 + d] ----
    float* op = outg + (size_t)b * NTOK * CDIM + (size_t)h * HD;
#pragma unroll
    for (int n = 0; n < 8; n++) {
        const int dcol = n * 8 + 2 * qc;
        *(float2*)&op[(size_t)row_lo * CDIM + dcol] = make_float2(O[n][0], O[n][1]);
        *(float2*)&op[(size_t)row_hi * CDIM + dcol] = make_float2(O[n][2], O[n][3]);
    }
}

extern "C" void kernel_launch(void* const* d_in, const int* in_sizes, int n_in,
                              void* d_out, int out_size) {
    const float* q1 = (const float*)d_in[0];
    const float* q2 = (const float*)d_in[1];
    const float* k1 = (const float*)d_in[2];
    const float* v1 = (const float*)d_in[3];
    // d_in[4] = k2 (unused by the reference math)
    const float* bias_table = (const float*)d_in[5];
    const float* gating     = (const float*)d_in[6];
    const int*   rel_index  = (const int*)d_in[7];
    float* out = (float*)d_out;

    bias_precompute<<<16, 256>>>(bias_table, rel_index);

    const int smem_bytes = (4 * NTOK * SQ + NTOK * SV) * (int)sizeof(float);  // 88064
    cudaFuncSetAttribute(win_attn_kernel,
                         cudaFuncAttributeMaxDynamicSharedMemorySize, smem_bytes);
    win_attn_kernel<<<NB * NH, 128, smem_bytes>>>(q1, q2, k1, v1, gating, out);
}